// round 1
// baseline (speedup 1.0000x reference)
#include <cuda_runtime.h>
#include <cuda_bf16.h>
#include <cstdint>
#include <math.h>

// Problem constants
#define B_BATCH 8
#define T_SEQ   2048
#define DIN     1024
#define DOUT    1024
#define M_TOTAL (B_BATCH * T_SEQ)   // 16384
#define GAMMA_F 0.9865f

// Scan chunking
#define NCH 16
#define CHUNK (T_SEQ / NCH)         // 128

// ---------------- device scratch (no cudaMalloc allowed) ----------------
__device__ float g_wksum[DIN];
__device__ float g_ksum[M_TOTAL];
__device__ float g_carry[B_BATCH][NCH][DIN];
__device__ float g_sv[(size_t)M_TOTAL * DIN];   // 64 MiB

// ---------------- kernel 1: wksum[d] = sum_e Wk[d][e] ----------------
__global__ void wksum_kernel(const float* __restrict__ Wk) {
    int d = blockIdx.x;
    float s = 0.f;
    for (int e = threadIdx.x; e < DOUT; e += 256)
        s += Wk[(size_t)d * DOUT + e];
    __shared__ float red[256];
    red[threadIdx.x] = s;
    __syncthreads();
    for (int o = 128; o > 0; o >>= 1) {
        if (threadIdx.x < o) red[threadIdx.x] += red[threadIdx.x + o];
        __syncthreads();
    }
    if (threadIdx.x == 0) g_wksum[d] = red[0];
}

// ---------------- kernel 2: ksum[m] = xk[m,:] . wksum  (zeroed at t==0) ----------------
__global__ void ksum_kernel(const float* __restrict__ xk) {
    int warp = threadIdx.x >> 5, lane = threadIdx.x & 31;
    int m = blockIdx.x * 8 + warp;
    const float* row = xk + (size_t)m * DIN;
    float s = 0.f;
    #pragma unroll 8
    for (int i = lane; i < DIN; i += 32)
        s += row[i] * g_wksum[i];
    #pragma unroll
    for (int o = 16; o; o >>= 1)
        s += __shfl_xor_sync(0xFFFFFFFFu, s, o);
    if (lane == 0) {
        int t = m & (T_SEQ - 1);
        g_ksum[m] = (t == 0) ? 0.f : s;   // u[b,0,:] = 0 per reference
    }
}

// ---------------- kernel 3a: per-chunk carries ----------------
// carry[b][ch][d] = sum_{t in chunk} gamma^{chunk_end-1-t} * ksum[b,t] * xv[b,t,d]
__global__ void scan_carry(const float* __restrict__ xv) {
    int ch = blockIdx.x, b = blockIdx.y;
    int d = blockIdx.z * 256 + threadIdx.x;
    const float* base = xv + ((size_t)b * T_SEQ + (size_t)ch * CHUNK) * DIN + d;
    const float* ks = g_ksum + b * T_SEQ + ch * CHUNK;
    float s = 0.f;
    #pragma unroll 8
    for (int t = 0; t < CHUNK; t++)
        s = GAMMA_F * s + ks[t] * base[(size_t)t * DIN];
    g_carry[b][ch][d] = s;
}

// ---------------- kernel 3b: combine carries + write sv ----------------
__global__ void scan_apply(const float* __restrict__ xv, float gammaC) {
    int ch = blockIdx.x, b = blockIdx.y;
    int d = blockIdx.z * 256 + threadIdx.x;
    // s0 = E_{ch-1}, E_c = carry[c] + gammaC * E_{c-1}
    float s = 0.f;
    for (int j = 0; j < ch; j++)
        s = s * gammaC + g_carry[b][j][d];
    const float* base = xv + ((size_t)b * T_SEQ + (size_t)ch * CHUNK) * DIN + d;
    const float* ks = g_ksum + b * T_SEQ + ch * CHUNK;
    float* out = g_sv + ((size_t)b * T_SEQ + (size_t)ch * CHUNK) * DIN + d;
    #pragma unroll 8
    for (int t = 0; t < CHUNK; t++) {
        s = GAMMA_F * s + ks[t] * base[(size_t)t * DIN];
        out[(size_t)t * DIN] = s;
    }
}

// ---------------- fused dual GEMM: O = (xq@Wq) .* (g_sv@Wv) ----------------
// bf16x3 split for fp32-grade precision on the tensor pipe.
// CTA tile 128x128, BK=32, 8 warps (2x4), warp tile 64x32, mma m16n8k16.

#define SMEM_STRIDE 40   // 32 + 8 bf16 pad

__device__ __forceinline__ void mma_bf16(float* c, const uint32_t* a, const uint32_t* b) {
    asm volatile(
        "mma.sync.aligned.m16n8k16.row.col.f32.bf16.bf16.f32 "
        "{%0,%1,%2,%3},{%4,%5,%6,%7},{%8,%9},{%0,%1,%2,%3};\n"
        : "+f"(c[0]), "+f"(c[1]), "+f"(c[2]), "+f"(c[3])
        : "r"(a[0]), "r"(a[1]), "r"(a[2]), "r"(a[3]), "r"(b[0]), "r"(b[1]));
}

__device__ __forceinline__ void split_bf16(float v, __nv_bfloat16& h, __nv_bfloat16& l) {
    h = __float2bfloat16(v);
    l = __float2bfloat16(v - __bfloat162float(h));
}

__device__ __forceinline__ void gemm_pass(
    const float* __restrict__ Aglob, const float* __restrict__ Wglob,
    int row0, int n0,
    __nv_bfloat16 (*Ahs)[SMEM_STRIDE], __nv_bfloat16 (*Als)[SMEM_STRIDE],
    __nv_bfloat16 (*Bhs)[SMEM_STRIDE], __nv_bfloat16 (*Bls)[SMEM_STRIDE],
    float acc[4][4][4])
{
    const int tid = threadIdx.x;
    const int warp = tid >> 5, lane = tid & 31;
    const int wm = warp >> 2, wn = warp & 3;
    const int g = lane >> 2, tg = lane & 3;

    for (int k0 = 0; k0 < DIN; k0 += 32) {
        __syncthreads();   // previous iter's fragments consumed
        // A tile: 128 rows x 32 cols fp32 -> split into hi/lo bf16 smem
        #pragma unroll
        for (int i = 0; i < 4; i++) {
            int slot = tid + i * 256;          // 0..1023
            int r = slot >> 3, c4 = slot & 7;  // 8 float4 per row
            float4 v = *(const float4*)(Aglob + (size_t)(row0 + r) * DIN + k0 + c4 * 4);
            float vv[4] = {v.x, v.y, v.z, v.w};
            #pragma unroll
            for (int j = 0; j < 4; j++) {
                __nv_bfloat16 h, l;
                split_bf16(vv[j], h, l);
                Ahs[r][c4 * 4 + j] = h;
                Als[r][c4 * 4 + j] = l;
            }
        }
        // B tile: 32 k-rows x 128 n-cols fp32, stored n-major in smem
        #pragma unroll
        for (int i = 0; i < 4; i++) {
            int slot = tid + i * 256;
            int kr = slot >> 5, c4 = slot & 31;   // 32 float4 per k-row
            float4 v = *(const float4*)(Wglob + (size_t)(k0 + kr) * DOUT + n0 + c4 * 4);
            float vv[4] = {v.x, v.y, v.z, v.w};
            #pragma unroll
            for (int j = 0; j < 4; j++) {
                __nv_bfloat16 h, l;
                split_bf16(vv[j], h, l);
                Bhs[c4 * 4 + j][kr] = h;
                Bls[c4 * 4 + j][kr] = l;
            }
        }
        __syncthreads();

        #pragma unroll
        for (int kk = 0; kk < 32; kk += 16) {
            uint32_t ah[4][4], al[4][4], bh[4][2], bl[4][2];
            #pragma unroll
            for (int i = 0; i < 4; i++) {
                int r = wm * 64 + i * 16;
                ah[i][0] = *(const uint32_t*)&Ahs[r + g    ][kk + 2 * tg    ];
                ah[i][1] = *(const uint32_t*)&Ahs[r + g + 8][kk + 2 * tg    ];
                ah[i][2] = *(const uint32_t*)&Ahs[r + g    ][kk + 2 * tg + 8];
                ah[i][3] = *(const uint32_t*)&Ahs[r + g + 8][kk + 2 * tg + 8];
                al[i][0] = *(const uint32_t*)&Als[r + g    ][kk + 2 * tg    ];
                al[i][1] = *(const uint32_t*)&Als[r + g + 8][kk + 2 * tg    ];
                al[i][2] = *(const uint32_t*)&Als[r + g    ][kk + 2 * tg + 8];
                al[i][3] = *(const uint32_t*)&Als[r + g + 8][kk + 2 * tg + 8];
            }
            #pragma unroll
            for (int j = 0; j < 4; j++) {
                int n = wn * 32 + j * 8 + g;
                bh[j][0] = *(const uint32_t*)&Bhs[n][kk + 2 * tg    ];
                bh[j][1] = *(const uint32_t*)&Bhs[n][kk + 2 * tg + 8];
                bl[j][0] = *(const uint32_t*)&Bls[n][kk + 2 * tg    ];
                bl[j][1] = *(const uint32_t*)&Bls[n][kk + 2 * tg + 8];
            }
            #pragma unroll
            for (int i = 0; i < 4; i++) {
                #pragma unroll
                for (int j = 0; j < 4; j++) {
                    mma_bf16(acc[i][j], ah[i], bh[j]);   // hi*hi
                    mma_bf16(acc[i][j], al[i], bh[j]);   // lo*hi
                    mma_bf16(acc[i][j], ah[i], bl[j]);   // hi*lo
                }
            }
        }
    }
}

__global__ __launch_bounds__(256, 1) void qs_gemm(
    const float* __restrict__ xq,
    const float* __restrict__ Wq,
    const float* __restrict__ Wv,
    float* __restrict__ out)
{
    __shared__ __align__(16) __nv_bfloat16 Ahs[128][SMEM_STRIDE];
    __shared__ __align__(16) __nv_bfloat16 Als[128][SMEM_STRIDE];
    __shared__ __align__(16) __nv_bfloat16 Bhs[128][SMEM_STRIDE];
    __shared__ __align__(16) __nv_bfloat16 Bls[128][SMEM_STRIDE];

    const int row0 = blockIdx.y * 128;
    const int n0 = blockIdx.x * 128;

    float accQ[4][4][4], accS[4][4][4];
    #pragma unroll
    for (int i = 0; i < 4; i++)
        #pragma unroll
        for (int j = 0; j < 4; j++)
            #pragma unroll
            for (int k = 0; k < 4; k++) { accQ[i][j][k] = 0.f; accS[i][j][k] = 0.f; }

    gemm_pass(xq,   Wq, row0, n0, Ahs, Als, Bhs, Bls, accQ);
    gemm_pass(g_sv, Wv, row0, n0, Ahs, Als, Bhs, Bls, accS);

    const int tid = threadIdx.x;
    const int warp = tid >> 5, lane = tid & 31;
    const int wm = warp >> 2, wn = warp & 3;
    const int g = lane >> 2, tg = lane & 3;

    #pragma unroll
    for (int i = 0; i < 4; i++) {
        #pragma unroll
        for (int j = 0; j < 4; j++) {
            int r = row0 + wm * 64 + i * 16;
            int c = n0 + wn * 32 + j * 8 + 2 * tg;
            out[(size_t)(r + g    ) * DOUT + c    ] = accQ[i][j][0] * accS[i][j][0];
            out[(size_t)(r + g    ) * DOUT + c + 1] = accQ[i][j][1] * accS[i][j][1];
            out[(size_t)(r + g + 8) * DOUT + c    ] = accQ[i][j][2] * accS[i][j][2];
            out[(size_t)(r + g + 8) * DOUT + c + 1] = accQ[i][j][3] * accS[i][j][3];
        }
    }
}

// ---------------- launch ----------------
extern "C" void kernel_launch(void* const* d_in, const int* in_sizes, int n_in,
                              void* d_out, int out_size)
{
    const float* xq = (const float*)d_in[0];
    const float* xk = (const float*)d_in[1];
    const float* xv = (const float*)d_in[2];
    const float* Wq = (const float*)d_in[3];
    const float* Wk = (const float*)d_in[4];
    const float* Wv = (const float*)d_in[5];
    float* out = (float*)d_out;

    float gammaC = (float)pow((double)GAMMA_F, (double)CHUNK);

    wksum_kernel<<<DIN, 256>>>(Wk);
    ksum_kernel<<<M_TOTAL / 8, 256>>>(xk);
    scan_carry<<<dim3(NCH, B_BATCH, DIN / 256), 256>>>(xv);
    scan_apply<<<dim3(NCH, B_BATCH, DIN / 256), 256>>>(xv, gammaC);
    qs_gemm<<<dim3(DOUT / 128, M_TOTAL / 128), 256>>>(xq, Wq, Wv, out);
}

// round 3
// speedup vs baseline: 2.3501x; 2.3501x over previous
#include <cuda_runtime.h>
#include <cuda_bf16.h>
#include <cstdint>
#include <math.h>

// Problem constants
#define B_BATCH 8
#define T_SEQ   2048
#define DIN     1024
#define DOUT    1024
#define M_TOTAL (B_BATCH * T_SEQ)   // 16384
#define GAMMA_F 0.9865f

// Scan chunking
#define NCH 32
#define CHUNK (T_SEQ / NCH)         // 64

// GEMM tiling: CTA 128x128, K-chunk 32, 8 warps (2x4), warp tile 64x32
#define SMEM_STRIDE 40              // bf16 elements per smem row (32 + 8 pad); 80 bytes
#define TILE_EB     (128 * SMEM_STRIDE * 2)      // 10240 bytes per tile
#define STAGE_BYTES (4 * TILE_EB)                // Ah, Al, Bh, Bl = 40960
#define NST 3
#define SMEM_TOTAL  (NST * STAGE_BYTES)          // 122880
#define NSTAGES 64                               // 2 GEMMs x 32 k-chunks

// ---------------- device scratch (no cudaMalloc allowed) ----------------
__device__ float g_wksum[DIN];
__device__ float g_ksum[M_TOTAL];
__device__ float g_carry[B_BATCH][NCH][DIN];
__device__ __nv_bfloat16 g_xq_hi[(size_t)M_TOTAL * DIN];
__device__ __nv_bfloat16 g_xq_lo[(size_t)M_TOTAL * DIN];
__device__ __nv_bfloat16 g_sv_hi[(size_t)M_TOTAL * DIN];
__device__ __nv_bfloat16 g_sv_lo[(size_t)M_TOTAL * DIN];
__device__ __nv_bfloat16 g_wqt_hi[(size_t)DIN * DOUT];   // [n][k]
__device__ __nv_bfloat16 g_wqt_lo[(size_t)DIN * DOUT];
__device__ __nv_bfloat16 g_wvt_hi[(size_t)DIN * DOUT];
__device__ __nv_bfloat16 g_wvt_lo[(size_t)DIN * DOUT];

// ---------------- helpers ----------------
__device__ __forceinline__ uint32_t smem_u32(const void* p) {
    uint32_t a;
    asm("{ .reg .u64 t; cvta.to.shared.u64 t, %1; cvt.u32.u64 %0, t; }" : "=r"(a) : "l"(p));
    return a;
}
__device__ __forceinline__ void cp16(uint32_t dst, const void* src) {
    asm volatile("cp.async.cg.shared.global [%0], [%1], 16;\n" :: "r"(dst), "l"(src));
}
__device__ __forceinline__ void mma_bf16(float* c, const uint32_t* a, const uint32_t* b) {
    asm volatile(
        "mma.sync.aligned.m16n8k16.row.col.f32.bf16.bf16.f32 "
        "{%0,%1,%2,%3},{%4,%5,%6,%7},{%8,%9},{%0,%1,%2,%3};\n"
        : "+f"(c[0]), "+f"(c[1]), "+f"(c[2]), "+f"(c[3])
        : "r"(a[0]), "r"(a[1]), "r"(a[2]), "r"(a[3]), "r"(b[0]), "r"(b[1]));
}
__device__ __forceinline__ void split_bf16(float v, __nv_bfloat16& h, __nv_bfloat16& l) {
    h = __float2bfloat16(v);
    l = __float2bfloat16(v - __bfloat162float(h));
}

// ---------------- kernel 1: wksum[d] = sum_e Wk[d][e] ----------------
__global__ void wksum_kernel(const float* __restrict__ Wk) {
    int d = blockIdx.x;
    float s = 0.f;
    for (int e = threadIdx.x; e < DOUT; e += 256)
        s += Wk[(size_t)d * DOUT + e];
    __shared__ float red[256];
    red[threadIdx.x] = s;
    __syncthreads();
    for (int o = 128; o > 0; o >>= 1) {
        if (threadIdx.x < o) red[threadIdx.x] += red[threadIdx.x + o];
        __syncthreads();
    }
    if (threadIdx.x == 0) g_wksum[d] = red[0];
}

// ---------------- kernel 2: ksum[m] = xk[m,:] . wksum ----------------
__global__ void ksum_kernel(const float* __restrict__ xk) {
    int warp = threadIdx.x >> 5, lane = threadIdx.x & 31;
    int m = blockIdx.x * 8 + warp;
    const float4* row = (const float4*)(xk + (size_t)m * DIN);
    const float4* wk = (const float4*)g_wksum;
    float s = 0.f;
    #pragma unroll
    for (int it = 0; it < 8; it++) {
        float4 a = row[lane + it * 32], w = wk[lane + it * 32];
        s += a.x * w.x + a.y * w.y + a.z * w.z + a.w * w.w;
    }
    #pragma unroll
    for (int o = 16; o; o >>= 1)
        s += __shfl_xor_sync(0xFFFFFFFFu, s, o);
    if (lane == 0) {
        int t = m & (T_SEQ - 1);
        g_ksum[m] = (t == 0) ? 0.f : s;
    }
}

// ---------------- split xq into bf16 hi/lo ----------------
__global__ void split_a_kernel(const float* __restrict__ src) {
    size_t idx = (size_t)blockIdx.x * 256 + threadIdx.x;   // float4 index
    float4 v = ((const float4*)src)[idx];
    float vv[4] = {v.x, v.y, v.z, v.w};
    __nv_bfloat16 h[4], l[4];
    #pragma unroll
    for (int j = 0; j < 4; j++) split_bf16(vv[j], h[j], l[j]);
    ((uint2*)g_xq_hi)[idx] = *(uint2*)h;
    ((uint2*)g_xq_lo)[idx] = *(uint2*)l;
}

// ---------------- transpose + split W: Wt[n][k] = W[k][n] ----------------
__global__ void wsplit_t_kernel(const float* __restrict__ W,
                                __nv_bfloat16* __restrict__ Th,
                                __nv_bfloat16* __restrict__ Tl) {
    __shared__ float tile[32][33];
    int n0 = blockIdx.x * 32, k0 = blockIdx.y * 32;
    for (int i = threadIdx.y; i < 32; i += 8)
        tile[i][threadIdx.x] = W[(size_t)(k0 + i) * DOUT + n0 + threadIdx.x];
    __syncthreads();
    for (int i = threadIdx.y; i < 32; i += 8) {
        float v = tile[threadIdx.x][i];          // = W[k0+tx][n0+i]
        __nv_bfloat16 h, l;
        split_bf16(v, h, l);
        size_t o = (size_t)(n0 + i) * DIN + k0 + threadIdx.x;
        Th[o] = h;
        Tl[o] = l;
    }
}

// ---------------- kernel 3a: per-chunk carries ----------------
__global__ void scan_carry(const float* __restrict__ xv) {
    int ch = blockIdx.x, b = blockIdx.y;
    int d = blockIdx.z * 256 + threadIdx.x;
    const float* base = xv + ((size_t)b * T_SEQ + (size_t)ch * CHUNK) * DIN + d;
    const float* ks = g_ksum + b * T_SEQ + ch * CHUNK;
    float s = 0.f;
    #pragma unroll 8
    for (int t = 0; t < CHUNK; t++)
        s = GAMMA_F * s + ks[t] * base[(size_t)t * DIN];
    g_carry[b][ch][d] = s;
}

// ---------------- kernel 3b: combine carries + write sv (split bf16) ----------------
__global__ void scan_apply(const float* __restrict__ xv, float gammaC) {
    int ch = blockIdx.x, b = blockIdx.y;
    int d = blockIdx.z * 256 + threadIdx.x;
    float s = 0.f;
    for (int j = 0; j < ch; j++)
        s = s * gammaC + g_carry[b][j][d];
    size_t base_off = ((size_t)b * T_SEQ + (size_t)ch * CHUNK) * DIN + d;
    const float* base = xv + base_off;
    const float* ks = g_ksum + b * T_SEQ + ch * CHUNK;
    #pragma unroll 8
    for (int t = 0; t < CHUNK; t++) {
        s = GAMMA_F * s + ks[t] * base[(size_t)t * DIN];
        __nv_bfloat16 h, l;
        split_bf16(s, h, l);
        g_sv_hi[base_off + (size_t)t * DIN] = h;
        g_sv_lo[base_off + (size_t)t * DIN] = l;
    }
}

// ---------------- fused dual GEMM: O = (xq@Wq) .* (sv@Wv) ----------------
// bf16x3 with pre-split operands, 3-stage cp.async pipeline, mma.sync HMMA.

__device__ __forceinline__ void load_tile_async(uint32_t sbase, const __nv_bfloat16* g,
                                                int row0, int k0, int tid) {
    const char* gb = (const char*)(g + (size_t)row0 * DIN + k0);
    #pragma unroll
    for (int i = 0; i < 2; i++) {
        int slot = tid + i * 256;            // 0..511
        int r = slot >> 2, c = slot & 3;     // 4 x 16B chunks per 64B row
        cp16(sbase + (uint32_t)(r * (SMEM_STRIDE * 2) + c * 16),
             gb + (size_t)r * (DIN * 2) + c * 16);
    }
}

__device__ __forceinline__ void mma_stage(const char* bufp, float acc[4][4][4],
                                          int wm, int wn, int g, int tg) {
    typedef const __nv_bfloat16 (*TileP)[SMEM_STRIDE];
    TileP Ahs = (TileP)(bufp);
    TileP Als = (TileP)(bufp + TILE_EB);
    TileP Bhs = (TileP)(bufp + 2 * TILE_EB);
    TileP Bls = (TileP)(bufp + 3 * TILE_EB);

    #pragma unroll
    for (int kk = 0; kk < 32; kk += 16) {
        uint32_t ah[4][4], al[4][4], bh[4][2], bl[4][2];
        #pragma unroll
        for (int i = 0; i < 4; i++) {
            int r = wm * 64 + i * 16;
            ah[i][0] = *(const uint32_t*)&Ahs[r + g    ][kk + 2 * tg    ];
            ah[i][1] = *(const uint32_t*)&Ahs[r + g + 8][kk + 2 * tg    ];
            ah[i][2] = *(const uint32_t*)&Ahs[r + g    ][kk + 2 * tg + 8];
            ah[i][3] = *(const uint32_t*)&Ahs[r + g + 8][kk + 2 * tg + 8];
            al[i][0] = *(const uint32_t*)&Als[r + g    ][kk + 2 * tg    ];
            al[i][1] = *(const uint32_t*)&Als[r + g + 8][kk + 2 * tg    ];
            al[i][2] = *(const uint32_t*)&Als[r + g    ][kk + 2 * tg + 8];
            al[i][3] = *(const uint32_t*)&Als[r + g + 8][kk + 2 * tg + 8];
        }
        #pragma unroll
        for (int j = 0; j < 4; j++) {
            int n = wn * 32 + j * 8 + g;
            bh[j][0] = *(const uint32_t*)&Bhs[n][kk + 2 * tg    ];
            bh[j][1] = *(const uint32_t*)&Bhs[n][kk + 2 * tg + 8];
            bl[j][0] = *(const uint32_t*)&Bls[n][kk + 2 * tg    ];
            bl[j][1] = *(const uint32_t*)&Bls[n][kk + 2 * tg + 8];
        }
        #pragma unroll
        for (int i = 0; i < 4; i++) {
            #pragma unroll
            for (int j = 0; j < 4; j++) {
                mma_bf16(acc[i][j], ah[i], bh[j]);   // hi*hi
                mma_bf16(acc[i][j], al[i], bh[j]);   // lo*hi
                mma_bf16(acc[i][j], ah[i], bl[j]);   // hi*lo
            }
        }
    }
}

__global__ __launch_bounds__(256, 1) void qs_gemm(float* __restrict__ out) {
    extern __shared__ char smem[];
    uint32_t sb = smem_u32(smem);
    const int tid = threadIdx.x;
    const int warp = tid >> 5, lane = tid & 31;
    const int wm = warp >> 2, wn = warp & 3;
    const int g = lane >> 2, tg = lane & 3;
    const int row0 = blockIdx.y * 128;
    const int n0 = blockIdx.x * 128;

    float accQ[4][4][4], accS[4][4][4];
    #pragma unroll
    for (int i = 0; i < 4; i++)
        #pragma unroll
        for (int j = 0; j < 4; j++)
            #pragma unroll
            for (int k = 0; k < 4; k++) { accQ[i][j][k] = 0.f; accS[i][j][k] = 0.f; }

    // issue loads for stage s (empty commit past the end keeps group counting uniform)
    auto issue = [&](int s) {
        if (s < NSTAGES) {
            int k0 = (s & 31) * 32;
            uint32_t bufb = sb + (uint32_t)(s % NST) * STAGE_BYTES;
            const __nv_bfloat16 *Ah, *Al, *Bh, *Bl;
            if (s < 32) { Ah = g_xq_hi; Al = g_xq_lo; Bh = g_wqt_hi; Bl = g_wqt_lo; }
            else        { Ah = g_sv_hi; Al = g_sv_lo; Bh = g_wvt_hi; Bl = g_wvt_lo; }
            load_tile_async(bufb,               Ah, row0, k0, tid);
            load_tile_async(bufb + TILE_EB,     Al, row0, k0, tid);
            load_tile_async(bufb + 2 * TILE_EB, Bh, n0,  k0, tid);
            load_tile_async(bufb + 3 * TILE_EB, Bl, n0,  k0, tid);
        }
        asm volatile("cp.async.commit_group;\n" ::: "memory");
    };

    issue(0);
    issue(1);

    for (int s = 0; s < NSTAGES; s++) {
        asm volatile("cp.async.wait_group 1;\n" ::: "memory");
        __syncthreads();           // stage s data visible; stage (s+2)%3 buffer free
        issue(s + 2);
        const char* bufp = smem + (s % NST) * STAGE_BYTES;
        if (s < 32) mma_stage(bufp, accQ, wm, wn, g, tg);
        else        mma_stage(bufp, accS, wm, wn, g, tg);
    }

    // epilogue: O = Q .* S
    #pragma unroll
    for (int i = 0; i < 4; i++) {
        #pragma unroll
        for (int j = 0; j < 4; j++) {
            int r = row0 + wm * 64 + i * 16;
            int c = n0 + wn * 32 + j * 8 + 2 * tg;
            float2 o0, o1;
            o0.x = accQ[i][j][0] * accS[i][j][0];
            o0.y = accQ[i][j][1] * accS[i][j][1];
            o1.x = accQ[i][j][2] * accS[i][j][2];
            o1.y = accQ[i][j][3] * accS[i][j][3];
            *(float2*)(out + (size_t)(r + g    ) * DOUT + c) = o0;
            *(float2*)(out + (size_t)(r + g + 8) * DOUT + c) = o1;
        }
    }
}

// ---------------- launch ----------------
extern "C" void kernel_launch(void* const* d_in, const int* in_sizes, int n_in,
                              void* d_out, int out_size)
{
    const float* xq = (const float*)d_in[0];
    const float* xk = (const float*)d_in[1];
    const float* xv = (const float*)d_in[2];
    const float* Wq = (const float*)d_in[3];
    const float* Wk = (const float*)d_in[4];
    const float* Wv = (const float*)d_in[5];
    float* out = (float*)d_out;

    float gammaC = (float)pow((double)GAMMA_F, (double)CHUNK);

    cudaFuncSetAttribute(qs_gemm, cudaFuncAttributeMaxDynamicSharedMemorySize, SMEM_TOTAL);

    __nv_bfloat16 *wqt_hi, *wqt_lo, *wvt_hi, *wvt_lo;
    cudaGetSymbolAddress((void**)&wqt_hi, g_wqt_hi);
    cudaGetSymbolAddress((void**)&wqt_lo, g_wqt_lo);
    cudaGetSymbolAddress((void**)&wvt_hi, g_wvt_hi);
    cudaGetSymbolAddress((void**)&wvt_lo, g_wvt_lo);

    wksum_kernel<<<DIN, 256>>>(Wk);
    ksum_kernel<<<M_TOTAL / 8, 256>>>(xk);
    split_a_kernel<<<(M_TOTAL * DIN / 4) / 256, 256>>>(xq);
    wsplit_t_kernel<<<dim3(32, 32), dim3(32, 8)>>>(Wq, wqt_hi, wqt_lo);
    wsplit_t_kernel<<<dim3(32, 32), dim3(32, 8)>>>(Wv, wvt_hi, wvt_lo);
    scan_carry<<<dim3(NCH, B_BATCH, DIN / 256), 256>>>(xv);
    scan_apply<<<dim3(NCH, B_BATCH, DIN / 256), 256>>>(xv, gammaC);
    qs_gemm<<<dim3(DOUT / 128, M_TOTAL / 128), 256, SMEM_TOTAL>>>(out);
}

// round 4
// speedup vs baseline: 3.2216x; 1.3708x over previous
#include <cuda_runtime.h>
#include <cuda_fp16.h>
#include <cstdint>
#include <math.h>

// Problem constants
#define B_BATCH 8
#define T_SEQ   2048
#define DIN     1024
#define DOUT    1024
#define M_TOTAL (B_BATCH * T_SEQ)   // 16384
#define GAMMA_F 0.9865f

// Scan chunking
#define NCH 32
#define CHUNK (T_SEQ / NCH)         // 64

// GEMM tiling: CTA 128x128, K-chunk 32, 8 warps (2x4), warp tile 64x32
// fp16 2-term: tiles per stage = {Ah, Al, Bh}
#define SMEM_STRIDE 40                            // fp16 elems/row (32 + 8 pad) = 80 B
#define TILE_EB     (128 * SMEM_STRIDE * 2)       // 10240 bytes
#define STAGE_BYTES (3 * TILE_EB)                 // 30720
#define NST 3
#define SMEM_TOTAL  (NST * STAGE_BYTES)           // 92160
#define NSTAGES 64                                // 2 GEMMs x 32 k-chunks

// ---------------- device scratch ----------------
__device__ float g_wksum[DIN];
__device__ float g_ksum[M_TOTAL];
__device__ float g_carry[B_BATCH][NCH][DIN];
__device__ __half g_xq_hi[(size_t)M_TOTAL * DIN];
__device__ __half g_xq_lo[(size_t)M_TOTAL * DIN];
__device__ __half g_sv_hi[(size_t)M_TOTAL * DIN];
__device__ __half g_sv_lo[(size_t)M_TOTAL * DIN];
__device__ __half g_wqt_hi[(size_t)DIN * DOUT];   // [n][k]
__device__ __half g_wvt_hi[(size_t)DIN * DOUT];

// ---------------- helpers ----------------
__device__ __forceinline__ uint32_t smem_u32(const void* p) {
    uint32_t a;
    asm("{ .reg .u64 t; cvta.to.shared.u64 t, %1; cvt.u32.u64 %0, t; }" : "=r"(a) : "l"(p));
    return a;
}
__device__ __forceinline__ void cp16(uint32_t dst, const void* src) {
    asm volatile("cp.async.cg.shared.global [%0], [%1], 16;\n" :: "r"(dst), "l"(src));
}
__device__ __forceinline__ void ldsm_x4(uint32_t* r, uint32_t addr) {
    asm volatile("ldmatrix.sync.aligned.m8n8.x4.shared.b16 {%0,%1,%2,%3}, [%4];"
                 : "=r"(r[0]), "=r"(r[1]), "=r"(r[2]), "=r"(r[3]) : "r"(addr));
}
__device__ __forceinline__ void mma_f16(float* c, const uint32_t* a, const uint32_t* b) {
    asm volatile(
        "mma.sync.aligned.m16n8k16.row.col.f32.f16.f16.f32 "
        "{%0,%1,%2,%3},{%4,%5,%6,%7},{%8,%9},{%0,%1,%2,%3};\n"
        : "+f"(c[0]), "+f"(c[1]), "+f"(c[2]), "+f"(c[3])
        : "r"(a[0]), "r"(a[1]), "r"(a[2]), "r"(a[3]), "r"(b[0]), "r"(b[1]));
}
__device__ __forceinline__ void split_h16(float v, __half& h, __half& l) {
    h = __float2half_rn(v);
    l = __float2half_rn(v - __half2float(h));
}

// ---------------- kernel 1: wksum[d] = sum_e Wk[d][e] ----------------
__global__ void wksum_kernel(const float* __restrict__ Wk) {
    int d = blockIdx.x;
    float s = 0.f;
    for (int e = threadIdx.x; e < DOUT; e += 256)
        s += Wk[(size_t)d * DOUT + e];
    __shared__ float red[256];
    red[threadIdx.x] = s;
    __syncthreads();
    for (int o = 128; o > 0; o >>= 1) {
        if (threadIdx.x < o) red[threadIdx.x] += red[threadIdx.x + o];
        __syncthreads();
    }
    if (threadIdx.x == 0) g_wksum[d] = red[0];
}

// ---------------- kernel 2: ksum[m] = xk[m,:] . wksum ----------------
__global__ void ksum_kernel(const float* __restrict__ xk) {
    int warp = threadIdx.x >> 5, lane = threadIdx.x & 31;
    int m = blockIdx.x * 8 + warp;
    const float4* row = (const float4*)(xk + (size_t)m * DIN);
    const float4* wk = (const float4*)g_wksum;
    float s = 0.f;
    #pragma unroll
    for (int it = 0; it < 8; it++) {
        float4 a = row[lane + it * 32], w = wk[lane + it * 32];
        s += a.x * w.x + a.y * w.y + a.z * w.z + a.w * w.w;
    }
    #pragma unroll
    for (int o = 16; o; o >>= 1)
        s += __shfl_xor_sync(0xFFFFFFFFu, s, o);
    if (lane == 0) {
        int t = m & (T_SEQ - 1);
        g_ksum[m] = (t == 0) ? 0.f : s;
    }
}

// ---------------- kernel 3 (fused prep): split xq; transpose+split Wq, Wv ----------------
// blocks [0, 16384): split xq (float4 per thread)
// blocks [16384, 17408): Wq transpose (32x32 tile per block)
// blocks [17408, 18432): Wv transpose
__global__ void prep_kernel(const float* __restrict__ xq,
                            const float* __restrict__ Wq,
                            const float* __restrict__ Wv) {
    int bx = blockIdx.x;
    int tid = threadIdx.x;
    if (bx < 16384) {
        size_t idx = (size_t)bx * 256 + tid;   // float4 index
        float4 v = ((const float4*)xq)[idx];
        float vv[4] = {v.x, v.y, v.z, v.w};
        __half h[4], l[4];
        #pragma unroll
        for (int j = 0; j < 4; j++) split_h16(vv[j], h[j], l[j]);
        ((uint2*)g_xq_hi)[idx] = *(uint2*)h;
        ((uint2*)g_xq_lo)[idx] = *(uint2*)l;
    } else {
        int b = bx - 16384;
        const float* W = (b < 1024) ? Wq : Wv;
        __half* Th = (b < 1024) ? g_wqt_hi : g_wvt_hi;
        b &= 1023;
        int n0 = (b & 31) * 32, k0 = (b >> 5) * 32;
        int tx = tid & 31, ty = tid >> 5;
        __shared__ float tile[32][33];
        for (int i = ty; i < 32; i += 8)
            tile[i][tx] = W[(size_t)(k0 + i) * DOUT + n0 + tx];
        __syncthreads();
        for (int i = ty; i < 32; i += 8)
            Th[(size_t)(n0 + i) * DIN + k0 + tx] = __float2half_rn(tile[tx][i]);
    }
}

// ---------------- kernel 4: per-chunk carries ----------------
__global__ void scan_carry(const float* __restrict__ xv) {
    int ch = blockIdx.x, b = blockIdx.y;
    int d = blockIdx.z * 256 + threadIdx.x;
    const float* base = xv + ((size_t)b * T_SEQ + (size_t)ch * CHUNK) * DIN + d;
    const float* ks = g_ksum + b * T_SEQ + ch * CHUNK;
    float s = 0.f;
    #pragma unroll 8
    for (int t = 0; t < CHUNK; t++)
        s = GAMMA_F * s + ks[t] * base[(size_t)t * DIN];
    g_carry[b][ch][d] = s;
}

// ---------------- kernel 5: combine carries + write sv (split fp16) ----------------
__global__ void scan_apply(const float* __restrict__ xv, float gammaC) {
    int ch = blockIdx.x, b = blockIdx.y;
    int d = blockIdx.z * 256 + threadIdx.x;
    float s = 0.f;
    for (int j = 0; j < ch; j++)
        s = s * gammaC + g_carry[b][j][d];
    size_t base_off = ((size_t)b * T_SEQ + (size_t)ch * CHUNK) * DIN + d;
    const float* base = xv + base_off;
    const float* ks = g_ksum + b * T_SEQ + ch * CHUNK;
    #pragma unroll 8
    for (int t = 0; t < CHUNK; t++) {
        s = GAMMA_F * s + ks[t] * base[(size_t)t * DIN];
        __half h, l;
        split_h16(s, h, l);
        g_sv_hi[base_off + (size_t)t * DIN] = h;
        g_sv_lo[base_off + (size_t)t * DIN] = l;
    }
}

// ---------------- fused dual GEMM: O = (xq@Wq) .* (sv@Wv) ----------------
// fp16 2-term (Ah*Bh + Al*Bh), ldmatrix fragments, 3-stage cp.async pipeline.

__device__ __forceinline__ void load_tile_async(uint32_t sbase, const __half* g,
                                                int row0, int k0, int tid) {
    const char* gb = (const char*)(g + (size_t)row0 * DIN + k0);
    #pragma unroll
    for (int i = 0; i < 2; i++) {
        int slot = tid + i * 256;            // 0..511
        int r = slot >> 2, c = slot & 3;     // 4 x 16B chunks per 64B row
        cp16(sbase + (uint32_t)(r * (SMEM_STRIDE * 2) + c * 16),
             gb + (size_t)r * (DIN * 2) + c * 16);
    }
}

__device__ __forceinline__ void mma_stage(uint32_t bufb, float acc[4][4][4],
                                          int wm, int wn, int lane) {
    // ldmatrix lane address components
    const int arow = lane & 15;                       // A: row within 16
    const int acol8 = (lane >> 4) * 8;                // A: k half select
    const int bnrow = ((lane >> 4) & 1) * 8 + (lane & 7);  // B: n within 16
    const int bcol8 = ((lane >> 3) & 1) * 8;          // B: k half select

    uint32_t Ah = bufb;
    uint32_t Al = bufb + TILE_EB;
    uint32_t Bh = bufb + 2 * TILE_EB;

    #pragma unroll
    for (int kk = 0; kk < 32; kk += 16) {
        uint32_t ah[4][4], al[4][4], bh[4][2];
        #pragma unroll
        for (int i = 0; i < 4; i++) {
            uint32_t aoff = (uint32_t)((wm * 64 + i * 16 + arow) * (SMEM_STRIDE * 2)
                                       + (kk + acol8) * 2);
            ldsm_x4(ah[i], Ah + aoff);
            ldsm_x4(al[i], Al + aoff);
        }
        #pragma unroll
        for (int j0 = 0; j0 < 4; j0 += 2) {
            uint32_t boff = (uint32_t)((wn * 32 + j0 * 8 + bnrow) * (SMEM_STRIDE * 2)
                                       + (kk + bcol8) * 2);
            uint32_t br[4];
            ldsm_x4(br, Bh + boff);
            bh[j0][0] = br[0]; bh[j0][1] = br[1];
            bh[j0 + 1][0] = br[2]; bh[j0 + 1][1] = br[3];
        }
        #pragma unroll
        for (int i = 0; i < 4; i++) {
            #pragma unroll
            for (int j = 0; j < 4; j++) {
                mma_f16(acc[i][j], ah[i], bh[j]);   // hi*hi
                mma_f16(acc[i][j], al[i], bh[j]);   // lo*hi
            }
        }
    }
}

__global__ __launch_bounds__(256, 1) void qs_gemm(float* __restrict__ out) {
    extern __shared__ char smem[];
    uint32_t sb = smem_u32(smem);
    const int tid = threadIdx.x;
    const int warp = tid >> 5, lane = tid & 31;
    const int wm = warp >> 2, wn = warp & 3;
    const int g = lane >> 2, tg = lane & 3;
    const int row0 = blockIdx.y * 128;
    const int n0 = blockIdx.x * 128;

    float accQ[4][4][4], accS[4][4][4];
    #pragma unroll
    for (int i = 0; i < 4; i++)
        #pragma unroll
        for (int j = 0; j < 4; j++)
            #pragma unroll
            for (int k = 0; k < 4; k++) { accQ[i][j][k] = 0.f; accS[i][j][k] = 0.f; }

    auto issue = [&](int s) {
        if (s < NSTAGES) {
            int k0 = (s & 31) * 32;
            uint32_t bufb = sb + (uint32_t)(s % NST) * STAGE_BYTES;
            const __half *Ah, *Al, *Bh;
            if (s < 32) { Ah = g_xq_hi; Al = g_xq_lo; Bh = g_wqt_hi; }
            else        { Ah = g_sv_hi; Al = g_sv_lo; Bh = g_wvt_hi; }
            load_tile_async(bufb,               Ah, row0, k0, tid);
            load_tile_async(bufb + TILE_EB,     Al, row0, k0, tid);
            load_tile_async(bufb + 2 * TILE_EB, Bh, n0,  k0, tid);
        }
        asm volatile("cp.async.commit_group;\n" ::: "memory");
    };

    issue(0);
    issue(1);

    for (int s = 0; s < NSTAGES; s++) {
        asm volatile("cp.async.wait_group 1;\n" ::: "memory");
        __syncthreads();           // stage s visible; buffer (s+2)%3 free
        issue(s + 2);
        uint32_t bufb = sb + (uint32_t)(s % NST) * STAGE_BYTES;
        if (s < 32) mma_stage(bufb, accQ, wm, wn, lane);
        else        mma_stage(bufb, accS, wm, wn, lane);
    }

    // epilogue: O = Q .* S
    #pragma unroll
    for (int i = 0; i < 4; i++) {
        #pragma unroll
        for (int j = 0; j < 4; j++) {
            int r = row0 + wm * 64 + i * 16;
            int c = n0 + wn * 32 + j * 8 + 2 * tg;
            float2 o0, o1;
            o0.x = accQ[i][j][0] * accS[i][j][0];
            o0.y = accQ[i][j][1] * accS[i][j][1];
            o1.x = accQ[i][j][2] * accS[i][j][2];
            o1.y = accQ[i][j][3] * accS[i][j][3];
            *(float2*)(out + (size_t)(r + g    ) * DOUT + c) = o0;
            *(float2*)(out + (size_t)(r + g + 8) * DOUT + c) = o1;
        }
    }
}

// ---------------- launch ----------------
extern "C" void kernel_launch(void* const* d_in, const int* in_sizes, int n_in,
                              void* d_out, int out_size)
{
    const float* xq = (const float*)d_in[0];
    const float* xk = (const float*)d_in[1];
    const float* xv = (const float*)d_in[2];
    const float* Wq = (const float*)d_in[3];
    const float* Wk = (const float*)d_in[4];
    const float* Wv = (const float*)d_in[5];
    float* out = (float*)d_out;

    float gammaC = (float)pow((double)GAMMA_F, (double)CHUNK);

    cudaFuncSetAttribute(qs_gemm, cudaFuncAttributeMaxDynamicSharedMemorySize, SMEM_TOTAL);

    wksum_kernel<<<DIN, 256>>>(Wk);                                   // 1
    ksum_kernel<<<M_TOTAL / 8, 256>>>(xk);                            // 2
    prep_kernel<<<16384 + 2048, 256>>>(xq, Wq, Wv);                   // 3
    scan_carry<<<dim3(NCH, B_BATCH, DIN / 256), 256>>>(xv);           // 4
    scan_apply<<<dim3(NCH, B_BATCH, DIN / 256), 256>>>(xv, gammaC);   // 5
    qs_gemm<<<dim3(DOUT / 128, M_TOTAL / 128), 256, SMEM_TOTAL>>>(out); // 6 (ncu -s 5 target)
}